// round 1
// baseline (speedup 1.0000x reference)
#include <cuda_runtime.h>

#define HDIM 4096
#define NEXP 64
#define BM   64
#define BK   64

typedef unsigned long long ull;

// Packed fp32x2 FMA (Blackwell): 2 fp32 MACs per instruction on the fma pipe.
__device__ __forceinline__ ull ffma2(ull a, ull b, ull c) {
    ull d;
    asm("fma.rn.f32x2 %0, %1, %2, %3;" : "=l"(d) : "l"(a), "l"(b), "l"(c));
    return d;
}
__device__ __forceinline__ ull pack2(float lo, float hi) {
    ull d;
    asm("mov.b64 %0, {%1, %2};" : "=l"(d) : "f"(lo), "f"(hi));
    return d;
}
__device__ __forceinline__ float f4c(const float4& v, int i) {
    return i == 0 ? v.x : (i == 1 ? v.y : (i == 2 ? v.z : v.w));
}

// Per-CTA z_loss partials (grid is fixed at T/BM = 256 CTAs).
__device__ float g_zpart[256];

__global__ __launch_bounds__(256) void router_kernel(
    const float* __restrict__ X, const float* __restrict__ W,
    float* __restrict__ out, int T)
{
    // Tiles and the logits buffer alias (static smem must stay < 48KB).
    __shared__ union {
        struct { float Xs[BK * BM]; float Ws[BK * NEXP]; } t;
        float Cs[BM * (NEXP + 1)];   // padded rows: stride 65 -> conflict-free row scan
    } sm;
    __shared__ float zred[BM];

    const int tid  = threadIdx.x;
    const int tx   = tid & 15;       // token group (4 tokens)
    const int ty   = tid >> 4;       // expert group (4 experts)
    const int tok0 = blockIdx.x * BM;

    // Loader mapping: each thread loads 4 rows x 1 float4 col-group for X and W,
    // register-transposes, stores along the row dim with an XOR swizzle.
    const int lm = tid & 15;            // k col-group (cols 4*lm..4*lm+3)
    const int lr = (tid >> 4) << 2;     // rows lr..lr+3
    const int tp = lr ^ (lm << 2);      // swizzled destination offset

    const float* xg = X + (size_t)(tok0 + lr) * HDIM + (lm << 2);
    const float* wg = W + (size_t)lr * HDIM + (lm << 2);

    // acc[token i][expert-pair ep]: f32x2 = (expert e0, expert e0+1)
    ull acc[4][2];
    #pragma unroll
    for (int i = 0; i < 4; ++i) { acc[i][0] = 0ull; acc[i][1] = 0ull; }

    for (int kt = 0; kt < HDIM; kt += BK) {
        float4 xv[4], wv[4];
        #pragma unroll
        for (int j = 0; j < 4; ++j) {
            xv[j] = *(const float4*)(xg + (size_t)j * HDIM + kt);
            wv[j] = *(const float4*)(wg + (size_t)j * HDIM + kt);
        }
        __syncthreads();   // previous chunk's compute done before overwrite
        #pragma unroll
        for (int ki = 0; ki < 4; ++ki) {
            const int krow = (lm << 2) + ki;
            float4 vx = make_float4(f4c(xv[0], ki), f4c(xv[1], ki), f4c(xv[2], ki), f4c(xv[3], ki));
            float4 vw = make_float4(f4c(wv[0], ki), f4c(wv[1], ki), f4c(wv[2], ki), f4c(wv[3], ki));
            *(float4*)&sm.t.Xs[krow * BM   + tp] = vx;
            *(float4*)&sm.t.Ws[krow * NEXP + tp] = vw;
        }
        __syncthreads();

        #pragma unroll
        for (int k = 0; k < BK; ++k) {
            const int s = (k >> 2) << 2;   // swizzle offset (multiple of 4)
            const float4     a = *(const float4*)    &sm.t.Xs[k * BM   + ((tx << 2) ^ s)];
            const ulonglong2 b = *(const ulonglong2*)&sm.t.Ws[k * NEXP + ((ty << 2) ^ s)];
            const ull a0 = pack2(a.x, a.x);
            const ull a1 = pack2(a.y, a.y);
            const ull a2 = pack2(a.z, a.z);
            const ull a3 = pack2(a.w, a.w);
            acc[0][0] = ffma2(a0, b.x, acc[0][0]);
            acc[0][1] = ffma2(a0, b.y, acc[0][1]);
            acc[1][0] = ffma2(a1, b.x, acc[1][0]);
            acc[1][1] = ffma2(a1, b.y, acc[1][1]);
            acc[2][0] = ffma2(a2, b.x, acc[2][0]);
            acc[2][1] = ffma2(a2, b.y, acc[2][1]);
            acc[3][0] = ffma2(a3, b.x, acc[3][0]);
            acc[3][1] = ffma2(a3, b.y, acc[3][1]);
        }
    }

    __syncthreads();   // all warps done reading tiles before Cs aliases them

    // Scatter logits to padded smem: Cs[token][expert]
    #pragma unroll
    for (int i = 0; i < 4; ++i) {
        #pragma unroll
        for (int ep = 0; ep < 2; ++ep) {
            const float lo = __uint_as_float((unsigned)(acc[i][ep] & 0xffffffffull));
            const float hi = __uint_as_float((unsigned)(acc[i][ep] >> 32));
            const int t_l = (tx << 2) + i;
            const int e0  = (ty << 2) + (ep << 1);
            sm.Cs[t_l * (NEXP + 1) + e0]     = lo;
            sm.Cs[t_l * (NEXP + 1) + e0 + 1] = hi;
        }
    }
    __syncthreads();

    // One thread per token: top-2 (JAX tie rule = lowest index first, strict '>'),
    // softmax scores, and z_loss partial.
    if (tid < BM) {
        const float* row = &sm.Cs[tid * (NEXP + 1)];
        float m1 = -3.4e38f, m2 = -3.4e38f;
        int i1 = 0, i2 = 0;
        #pragma unroll
        for (int e = 0; e < NEXP; ++e) {
            const float v = row[e];
            if (v > m1)      { m2 = m1; i2 = i1; m1 = v; i1 = e; }
            else if (v > m2) { m2 = v; i2 = e; }
        }
        float ssum = 0.f, sq = 0.f;
        #pragma unroll
        for (int e = 0; e < NEXP; ++e) {
            const float v = row[e];
            ssum += expf(v - m1);
            sq = fmaf(v, v, sq);
        }
        const int g = tok0 + tid;
        const float inv = 1.0f / ssum;
        // Output layout: idx[T*2] | scores[T*2] | aux | z   (all fp32)
        out[2 * g + 0] = (float)i1;
        out[2 * g + 1] = (float)i2;
        out[2 * T + 2 * g + 0] = inv;                   // exp(m1-m1)/sum
        out[2 * T + 2 * g + 1] = expf(m2 - m1) * inv;
        zred[tid] = sq;
    }
    __syncthreads();
    if (tid == 0) {
        float s = 0.f;
        #pragma unroll
        for (int i = 0; i < BM; ++i) s += zred[i];
        g_zpart[blockIdx.x] = s;   // deterministic: fixed-order reduce, no atomics
    }
}

__global__ void finalize_kernel(float* __restrict__ out, int T) {
    if (threadIdx.x == 0 && blockIdx.x == 0) {
        float s = 0.f;
        for (int i = 0; i < 256; ++i) s += g_zpart[i];
        out[4 * T + 0] = 0.0f;                              // aux_loss
        out[4 * T + 1] = s / ((float)T * (float)NEXP);      // z_loss
    }
}

extern "C" void kernel_launch(void* const* d_in, const int* in_sizes, int n_in,
                              void* d_out, int out_size) {
    const float* X = (const float*)d_in[0];   // [B*S, H] fp32
    const float* W = (const float*)d_in[1];   // [E, H] fp32
    float* out = (float*)d_out;
    const int T = in_sizes[0] / HDIM;         // 16384 tokens
    router_kernel<<<T / BM, 256>>>(X, W, out, T);
    finalize_kernel<<<1, 32>>>(out, T);
}

// round 3
// speedup vs baseline: 1.4403x; 1.4403x over previous
#include <cuda_runtime.h>
#include <cuda_fp16.h>
#include <cstdint>

#define HDIM 4096
#define NEXP 64
#define BM   128      // tokens per CTA
#define BK   64       // k-chunk
#define TPAD 72       // padded halves per smem row (144B -> conflict-free ldmatrix)

// dynamic smem layout (bytes), double buffered
#define XH_OFF 0
#define XL_OFF (BM * TPAD * 2)                  // 18432
#define WH_OFF (2 * BM * TPAD * 2)              // 36864
#define WL_OFF (WH_OFF + NEXP * TPAD * 2)       // 46080
#define BUF_BYTES (WL_OFF + NEXP * TPAD * 2)    // 55296
#define SMEM_TOTAL (2 * BUF_BYTES)              // 110592

__device__ float    g_z[BM];      // 128 CTA partials (grid = 128)
__device__ unsigned g_cnt = 0;

// split one fp32 pair into fp16 hi (rn) + fp16 lo (rn of residual), packed b32 each
__device__ __forceinline__ void split2(float f0, float f1, unsigned& hi, unsigned& lo) {
    __half2 h = __floats2half2_rn(f0, f1);
    float2 hf = __half22float2(h);
    __half2 l = __floats2half2_rn(f0 - hf.x, f1 - hf.y);
    hi = *reinterpret_cast<unsigned*>(&h);
    lo = *reinterpret_cast<unsigned*>(&l);
}

__device__ __forceinline__ void ldsm4(unsigned* d, uint32_t addr) {
    asm volatile("ldmatrix.sync.aligned.m8n8.x4.shared.b16 {%0,%1,%2,%3}, [%4];"
                 : "=r"(d[0]), "=r"(d[1]), "=r"(d[2]), "=r"(d[3]) : "r"(addr));
}
__device__ __forceinline__ void mma16816(float* c, const unsigned* a, unsigned b0, unsigned b1) {
    asm volatile("mma.sync.aligned.m16n8k16.row.col.f32.f16.f16.f32 "
                 "{%0,%1,%2,%3}, {%4,%5,%6,%7}, {%8,%9}, {%0,%1,%2,%3};"
                 : "+f"(c[0]), "+f"(c[1]), "+f"(c[2]), "+f"(c[3])
                 : "r"(a[0]), "r"(a[1]), "r"(a[2]), "r"(a[3]), "r"(b0), "r"(b1));
}

__global__ __launch_bounds__(256, 1) void router_mma(
    const float* __restrict__ X, const float* __restrict__ W,
    float* __restrict__ out, int T)
{
    extern __shared__ char smem[];
    __shared__ float zred[BM];
    const uint32_t sb = (uint32_t)__cvta_generic_to_shared(smem);

    const int tid  = threadIdx.x;
    const int lane = tid & 31;
    const int warp = tid >> 5;
    const int tok0 = blockIdx.x * BM;

    // ---- global loaders ----
    const int xr = tid >> 1, xc = (tid & 1) * 32;   // X: 2 thr/row, 32 floats each
    const int wr = tid >> 2, wc = (tid & 3) * 16;   // W: 4 thr/row, 16 floats each
    const float* xg = X + (size_t)(tok0 + xr) * HDIM + xc;
    const float* wg = W + (size_t)wr * HDIM + wc;

    // ---- ldmatrix per-lane offsets ----
    const int g = lane >> 3, r = lane & 7;
    const int m0 = warp * 16;
    // A (row-major [m][k]): matrices = (rows0-7,k0) (rows8-15,k0) (rows0-7,k8) (rows8-15,k8)
    const uint32_t aOff = (uint32_t)(((m0 + r + ((g & 1) << 3)) * TPAD + ((g >> 1) << 3)) * 2);
    // B stored [n][k] row-major: NON-trans ldmatrix already yields the mma B fragment.
    // matrices = (n0-7,k0) (n0-7,k8) (n8-15,k0) (n8-15,k8) -> regs {b0,b1,b2,b3}
    const int bRow = r + ((g >> 1) << 3);
    const int bK   = (g & 1) << 3;

    float acc[8][4];
    #pragma unroll
    for (int i = 0; i < 8; ++i)
        #pragma unroll
        for (int j = 0; j < 4; ++j) acc[i][j] = 0.f;

    float4 xv[8], wv[4];

    // ---- preload + convert chunk 0 ----
    #pragma unroll
    for (int j = 0; j < 8; ++j) xv[j] = *(const float4*)(xg + j * 4);
    #pragma unroll
    for (int j = 0; j < 4; ++j) wv[j] = *(const float4*)(wg + j * 4);

    int p = 0;
    {
        char* buf = smem;  // buffer 0
        #pragma unroll
        for (int jj = 0; jj < 4; ++jj) {
            float4 a = xv[2 * jj], b = xv[2 * jj + 1];
            uint4 hv, lv;
            split2(a.x, a.y, hv.x, lv.x); split2(a.z, a.w, hv.y, lv.y);
            split2(b.x, b.y, hv.z, lv.z); split2(b.z, b.w, hv.w, lv.w);
            const int off = (xr * TPAD + xc + 8 * jj) * 2;
            *(uint4*)(buf + XH_OFF + off) = hv;
            *(uint4*)(buf + XL_OFF + off) = lv;
        }
        #pragma unroll
        for (int jj = 0; jj < 2; ++jj) {
            float4 a = wv[2 * jj], b = wv[2 * jj + 1];
            uint4 hv, lv;
            split2(a.x * 64.f, a.y * 64.f, hv.x, lv.x); split2(a.z * 64.f, a.w * 64.f, hv.y, lv.y);
            split2(b.x * 64.f, b.y * 64.f, hv.z, lv.z); split2(b.z * 64.f, b.w * 64.f, hv.w, lv.w);
            const int off = (wr * TPAD + wc + 8 * jj) * 2;
            *(uint4*)(buf + WH_OFF + off) = hv;
            *(uint4*)(buf + WL_OFF + off) = lv;
        }
    }
    __syncthreads();

    // ---- main loop: prefetch k+1, MMA k, convert->other buffer ----
    for (int kt = BK; kt <= HDIM; kt += BK) {
        if (kt < HDIM) {
            #pragma unroll
            for (int j = 0; j < 8; ++j) xv[j] = *(const float4*)(xg + kt + j * 4);
            #pragma unroll
            for (int j = 0; j < 4; ++j) wv[j] = *(const float4*)(wg + kt + j * 4);
        }

        // MMA over buffer p
        {
            const uint32_t base = sb + (uint32_t)(p * BUF_BYTES);
            #pragma unroll
            for (int ks = 0; ks < 4; ++ks) {
                unsigned ah[4], al[4];
                ldsm4(ah, base + XH_OFF + aOff + ks * 32);
                ldsm4(al, base + XL_OFF + aOff + ks * 32);
                #pragma unroll
                for (int nt = 0; nt < 4; ++nt) {
                    const uint32_t boff = (uint32_t)(((nt * 16 + bRow) * TPAD + bK) * 2 + ks * 32);
                    unsigned bh[4], bl[4];
                    ldsm4(bh, base + WH_OFF + boff);
                    ldsm4(bl, base + WL_OFF + boff);
                    mma16816(acc[2 * nt],     ah, bh[0], bh[1]);
                    mma16816(acc[2 * nt],     al, bh[0], bh[1]);
                    mma16816(acc[2 * nt],     ah, bl[0], bl[1]);
                    mma16816(acc[2 * nt + 1], ah, bh[2], bh[3]);
                    mma16816(acc[2 * nt + 1], al, bh[2], bh[3]);
                    mma16816(acc[2 * nt + 1], ah, bl[2], bl[3]);
                }
            }
        }

        if (kt < HDIM) {
            char* buf = smem + (p ^ 1) * BUF_BYTES;
            #pragma unroll
            for (int jj = 0; jj < 4; ++jj) {
                float4 a = xv[2 * jj], b = xv[2 * jj + 1];
                uint4 hv, lv;
                split2(a.x, a.y, hv.x, lv.x); split2(a.z, a.w, hv.y, lv.y);
                split2(b.x, b.y, hv.z, lv.z); split2(b.z, b.w, hv.w, lv.w);
                const int off = (xr * TPAD + xc + 8 * jj) * 2;
                *(uint4*)(buf + XH_OFF + off) = hv;
                *(uint4*)(buf + XL_OFF + off) = lv;
            }
            #pragma unroll
            for (int jj = 0; jj < 2; ++jj) {
                float4 a = wv[2 * jj], b = wv[2 * jj + 1];
                uint4 hv, lv;
                split2(a.x * 64.f, a.y * 64.f, hv.x, lv.x); split2(a.z * 64.f, a.w * 64.f, hv.y, lv.y);
                split2(b.x * 64.f, b.y * 64.f, hv.z, lv.z); split2(b.z * 64.f, b.w * 64.f, hv.w, lv.w);
                const int off = (wr * TPAD + wc + 8 * jj) * 2;
                *(uint4*)(buf + WH_OFF + off) = hv;
                *(uint4*)(buf + WL_OFF + off) = lv;
            }
            __syncthreads();
            p ^= 1;
        }
    }

    __syncthreads();   // all MMA smem reads done before logits alias buffers

    // ---- scatter logits (scaled back by 1/64) to padded smem ----
    float* cs = (float*)smem;                 // [BM][65]
    const float inv64 = 0.015625f;
    const int qr = lane >> 2;
    const int qc = (lane & 3) * 2;
    #pragma unroll
    for (int nt = 0; nt < 8; ++nt) {
        const int col = nt * 8 + qc;
        cs[(m0 + qr)     * 65 + col]     = acc[nt][0] * inv64;
        cs[(m0 + qr)     * 65 + col + 1] = acc[nt][1] * inv64;
        cs[(m0 + qr + 8) * 65 + col]     = acc[nt][2] * inv64;
        cs[(m0 + qr + 8) * 65 + col + 1] = acc[nt][3] * inv64;
    }
    __syncthreads();

    // ---- per-token top-2 / softmax / z partial (threads 0..127) ----
    if (tid < BM) {
        const float* row = &cs[tid * 65];
        float m1 = -3.4e38f, m2 = -3.4e38f;
        int i1 = 0, i2 = 0;
        #pragma unroll
        for (int e = 0; e < NEXP; ++e) {
            const float v = row[e];
            if (v > m1)      { m2 = m1; i2 = i1; m1 = v; i1 = e; }
            else if (v > m2) { m2 = v; i2 = e; }
        }
        float ssum = 0.f, sq = 0.f;
        #pragma unroll
        for (int e = 0; e < NEXP; ++e) {
            const float v = row[e];
            ssum += expf(v - m1);
            sq = fmaf(v, v, sq);
        }
        const int gi = tok0 + tid;
        const float inv = 1.0f / ssum;
        out[2 * gi + 0] = (float)i1;
        out[2 * gi + 1] = (float)i2;
        out[2 * T + 2 * gi + 0] = inv;
        out[2 * T + 2 * gi + 1] = expf(m2 - m1) * inv;
        zred[tid] = sq;
    }
    __syncthreads();

    // ---- deterministic z_loss: per-CTA fixed-order sum, last CTA reduces ----
    if (tid == 0) {
        float s = 0.f;
        #pragma unroll
        for (int i = 0; i < BM; ++i) s += zred[i];
        g_z[blockIdx.x] = s;
        __threadfence();
        const unsigned t = atomicAdd(&g_cnt, 1);
        if (t == gridDim.x - 1) {
            float z = 0.f;
            for (unsigned i = 0; i < gridDim.x; ++i) z += g_z[i];
            out[4 * T + 0] = 0.0f;
            out[4 * T + 1] = z / ((float)T * (float)NEXP);
            g_cnt = 0;     // reset for next graph replay
        }
    }
}

extern "C" void kernel_launch(void* const* d_in, const int* in_sizes, int n_in,
                              void* d_out, int out_size) {
    const float* X = (const float*)d_in[0];   // [B*S, H] fp32
    const float* W = (const float*)d_in[1];   // [E, H] fp32
    float* out = (float*)d_out;
    const int T = in_sizes[0] / HDIM;         // 16384
    cudaFuncSetAttribute(router_mma, cudaFuncAttributeMaxDynamicSharedMemorySize, SMEM_TOTAL);
    router_mma<<<T / BM, 256, SMEM_TOTAL>>>(X, W, out, T);
}

// round 4
// speedup vs baseline: 2.1035x; 1.4605x over previous
#include <cuda_runtime.h>
#include <cuda_fp16.h>
#include <cstdint>

#define HDIM 4096
#define NEXP 64
#define BM   128      // tokens per CTA
#define BK   64       // k-chunk
#define TPAD 72       // padded halves per smem row (144B -> conflict-free ldmatrix)
#define NTHR 512

// dynamic smem layout (bytes), double buffered
#define XH_OFF 0
#define XL_OFF (BM * TPAD * 2)                  // 18432
#define WH_OFF (2 * BM * TPAD * 2)              // 36864
#define WL_OFF (WH_OFF + NEXP * TPAD * 2)       // 46080
#define BUF_BYTES (WL_OFF + NEXP * TPAD * 2)    // 55296
#define SMEM_TOTAL (2 * BUF_BYTES)              // 110592

__device__ float    g_z[128];     // per-CTA z partials (grid = 128)
__device__ unsigned g_cnt = 0;

// split one fp32 pair into fp16 hi (rn) + fp16 lo (rn of residual), packed b32 each
__device__ __forceinline__ void split2(float f0, float f1, unsigned& hi, unsigned& lo) {
    __half2 h = __floats2half2_rn(f0, f1);
    float2 hf = __half22float2(h);
    __half2 l = __floats2half2_rn(f0 - hf.x, f1 - hf.y);
    hi = *reinterpret_cast<unsigned*>(&h);
    lo = *reinterpret_cast<unsigned*>(&l);
}

__device__ __forceinline__ void ldsm4(unsigned* d, uint32_t addr) {
    asm volatile("ldmatrix.sync.aligned.m8n8.x4.shared.b16 {%0,%1,%2,%3}, [%4];"
                 : "=r"(d[0]), "=r"(d[1]), "=r"(d[2]), "=r"(d[3]) : "r"(addr));
}
__device__ __forceinline__ void mma16816(float* c, const unsigned* a, unsigned b0, unsigned b1) {
    asm volatile("mma.sync.aligned.m16n8k16.row.col.f32.f16.f16.f32 "
                 "{%0,%1,%2,%3}, {%4,%5,%6,%7}, {%8,%9}, {%0,%1,%2,%3};"
                 : "+f"(c[0]), "+f"(c[1]), "+f"(c[2]), "+f"(c[3])
                 : "r"(a[0]), "r"(a[1]), "r"(a[2]), "r"(a[3]), "r"(b0), "r"(b1));
}

__global__ __launch_bounds__(NTHR, 1) void router_mma(
    const float* __restrict__ X, const float* __restrict__ W,
    float* __restrict__ out, int T)
{
    extern __shared__ char smem[];
    __shared__ float zred[BM];
    const uint32_t sb = (uint32_t)__cvta_generic_to_shared(smem);

    const int tid  = threadIdx.x;
    const int lane = tid & 31;
    const int warp = tid >> 5;          // 0..15
    const int tok0 = blockIdx.x * BM;

    // ---- global loaders (512 threads) ----
    const int xr = tid >> 2, xc = (tid & 3) * 16;   // X: 4 thr/row, 16 floats each
    const int wr = tid >> 3, wc = (tid & 7) * 8;    // W: 8 thr/row,  8 floats each
    const float* xg = X + (size_t)(tok0 + xr) * HDIM + xc;
    const float* wg = W + (size_t)wr * HDIM + wc;

    // ---- warp tiling: 8 M-groups x 2 N-halves ----
    const int m0 = (warp & 7) * 16;     // token rows m0..m0+15
    const int n0 = (warp >> 3) * 32;    // expert cols n0..n0+31

    // ---- ldmatrix per-lane offsets ----
    const int g = lane >> 3, r = lane & 7;
    // A (row-major [m][k]): matrices = (rows0-7,k0)(rows8-15,k0)(rows0-7,k8)(rows8-15,k8)
    const uint32_t aOff = (uint32_t)(((m0 + r + ((g & 1) << 3)) * TPAD + ((g >> 1) << 3)) * 2);
    // B stored [n][k] row-major: non-trans ldmatrix yields the mma B fragment directly.
    const int bRow = r + ((g >> 1) << 3);
    const int bK   = (g & 1) << 3;

    float acc[4][4];                    // acc[j] covers n = n0 + 8*j
    #pragma unroll
    for (int i = 0; i < 4; ++i)
        #pragma unroll
        for (int j = 0; j < 4; ++j) acc[i][j] = 0.f;

    float4 xv[4], wv[2];

    // ---- preload + convert chunk 0 ----
    #pragma unroll
    for (int j = 0; j < 4; ++j) xv[j] = *(const float4*)(xg + j * 4);
    #pragma unroll
    for (int j = 0; j < 2; ++j) wv[j] = *(const float4*)(wg + j * 4);

    int p = 0;
    {
        char* buf = smem;
        #pragma unroll
        for (int jj = 0; jj < 2; ++jj) {
            float4 a = xv[2 * jj], b = xv[2 * jj + 1];
            uint4 hv, lv;
            split2(a.x, a.y, hv.x, lv.x); split2(a.z, a.w, hv.y, lv.y);
            split2(b.x, b.y, hv.z, lv.z); split2(b.z, b.w, hv.w, lv.w);
            const int off = (xr * TPAD + xc + 8 * jj) * 2;
            *(uint4*)(buf + XH_OFF + off) = hv;
            *(uint4*)(buf + XL_OFF + off) = lv;
        }
        {
            float4 a = wv[0], b = wv[1];
            uint4 hv, lv;
            split2(a.x * 64.f, a.y * 64.f, hv.x, lv.x); split2(a.z * 64.f, a.w * 64.f, hv.y, lv.y);
            split2(b.x * 64.f, b.y * 64.f, hv.z, lv.z); split2(b.z * 64.f, b.w * 64.f, hv.w, lv.w);
            const int off = (wr * TPAD + wc) * 2;
            *(uint4*)(buf + WH_OFF + off) = hv;
            *(uint4*)(buf + WL_OFF + off) = lv;
        }
    }
    __syncthreads();

    // ---- main loop: prefetch k+1, MMA k, convert->other buffer ----
    for (int kt = BK; kt <= HDIM; kt += BK) {
        if (kt < HDIM) {
            #pragma unroll
            for (int j = 0; j < 4; ++j) xv[j] = *(const float4*)(xg + kt + j * 4);
            #pragma unroll
            for (int j = 0; j < 2; ++j) wv[j] = *(const float4*)(wg + kt + j * 4);
        }

        // MMA over buffer p
        {
            const uint32_t base = sb + (uint32_t)(p * BUF_BYTES);
            #pragma unroll
            for (int ks = 0; ks < 4; ++ks) {
                unsigned ah[4], al[4];
                ldsm4(ah, base + XH_OFF + aOff + ks * 32);
                ldsm4(al, base + XL_OFF + aOff + ks * 32);
                #pragma unroll
                for (int nt = 0; nt < 2; ++nt) {
                    const uint32_t boff = (uint32_t)(((n0 + nt * 16 + bRow) * TPAD + bK) * 2 + ks * 32);
                    unsigned bh[4], bl[4];
                    ldsm4(bh, base + WH_OFF + boff);
                    ldsm4(bl, base + WL_OFF + boff);
                    mma16816(acc[2 * nt],     ah, bh[0], bh[1]);
                    mma16816(acc[2 * nt],     al, bh[0], bh[1]);
                    mma16816(acc[2 * nt],     ah, bl[0], bl[1]);
                    mma16816(acc[2 * nt + 1], ah, bh[2], bh[3]);
                    mma16816(acc[2 * nt + 1], al, bh[2], bh[3]);
                    mma16816(acc[2 * nt + 1], ah, bl[2], bl[3]);
                }
            }
        }

        if (kt < HDIM) {
            char* buf = smem + (p ^ 1) * BUF_BYTES;
            #pragma unroll
            for (int jj = 0; jj < 2; ++jj) {
                float4 a = xv[2 * jj], b = xv[2 * jj + 1];
                uint4 hv, lv;
                split2(a.x, a.y, hv.x, lv.x); split2(a.z, a.w, hv.y, lv.y);
                split2(b.x, b.y, hv.z, lv.z); split2(b.z, b.w, hv.w, lv.w);
                const int off = (xr * TPAD + xc + 8 * jj) * 2;
                *(uint4*)(buf + XH_OFF + off) = hv;
                *(uint4*)(buf + XL_OFF + off) = lv;
            }
            {
                float4 a = wv[0], b = wv[1];
                uint4 hv, lv;
                split2(a.x * 64.f, a.y * 64.f, hv.x, lv.x); split2(a.z * 64.f, a.w * 64.f, hv.y, lv.y);
                split2(b.x * 64.f, b.y * 64.f, hv.z, lv.z); split2(b.z * 64.f, b.w * 64.f, hv.w, lv.w);
                const int off = (wr * TPAD + wc) * 2;
                *(uint4*)(buf + WH_OFF + off) = hv;
                *(uint4*)(buf + WL_OFF + off) = lv;
            }
            __syncthreads();
            p ^= 1;
        }
    }

    __syncthreads();   // all MMA smem reads done before logits alias buffers

    // ---- scatter logits (scaled back by 1/64) to padded smem ----
    float* cs = (float*)smem;                 // [BM][65]
    const float inv64 = 0.015625f;
    const int qr = lane >> 2;
    const int qc = (lane & 3) * 2;
    #pragma unroll
    for (int j = 0; j < 4; ++j) {
        const int col = n0 + j * 8 + qc;
        cs[(m0 + qr)     * 65 + col]     = acc[j][0] * inv64;
        cs[(m0 + qr)     * 65 + col + 1] = acc[j][1] * inv64;
        cs[(m0 + qr + 8) * 65 + col]     = acc[j][2] * inv64;
        cs[(m0 + qr + 8) * 65 + col + 1] = acc[j][3] * inv64;
    }
    __syncthreads();

    // ---- per-token top-2 / softmax / z partial (threads 0..127) ----
    if (tid < BM) {
        const float* row = &cs[tid * 65];
        float m1 = -3.4e38f, m2 = -3.4e38f;
        int i1 = 0, i2 = 0;
        #pragma unroll
        for (int e = 0; e < NEXP; ++e) {
            const float v = row[e];
            if (v > m1)      { m2 = m1; i2 = i1; m1 = v; i1 = e; }
            else if (v > m2) { m2 = v; i2 = e; }
        }
        float ssum = 0.f, sq = 0.f;
        #pragma unroll
        for (int e = 0; e < NEXP; ++e) {
            const float v = row[e];
            ssum += expf(v - m1);
            sq = fmaf(v, v, sq);
        }
        const int gi = tok0 + tid;
        const float inv = 1.0f / ssum;
        out[2 * gi + 0] = (float)i1;
        out[2 * gi + 1] = (float)i2;
        out[2 * T + 2 * gi + 0] = inv;
        out[2 * T + 2 * gi + 1] = expf(m2 - m1) * inv;
        zred[tid] = sq;
    }
    __syncthreads();

    // ---- deterministic z_loss: per-CTA fixed-order sum, last CTA reduces ----
    if (tid == 0) {
        float s = 0.f;
        #pragma unroll
        for (int i = 0; i < BM; ++i) s += zred[i];
        g_z[blockIdx.x] = s;
        __threadfence();
        const unsigned t = atomicAdd(&g_cnt, 1);
        if (t == gridDim.x - 1) {
            float z = 0.f;
            for (unsigned i = 0; i < gridDim.x; ++i) z += g_z[i];
            out[4 * T + 0] = 0.0f;
            out[4 * T + 1] = z / ((float)T * (float)NEXP);
            g_cnt = 0;     // reset for next graph replay
        }
    }
}

extern "C" void kernel_launch(void* const* d_in, const int* in_sizes, int n_in,
                              void* d_out, int out_size) {
    const float* X = (const float*)d_in[0];   // [B*S, H] fp32
    const float* W = (const float*)d_in[1];   // [E, H] fp32
    float* out = (float*)d_out;
    const int T = in_sizes[0] / HDIM;         // 16384
    cudaFuncSetAttribute(router_mma, cudaFuncAttributeMaxDynamicSharedMemorySize, SMEM_TOTAL);
    router_mma<<<T / BM, NTHR, SMEM_TOTAL>>>(X, W, out, T);
}